// round 3
// baseline (speedup 1.0000x reference)
#include <cuda_runtime.h>
#include <cuda_bf16.h>
#include <math.h>

// LRML memory-network scoring, 8-lanes-per-element layout.
//  0: user_ids  int32  [B]
//  1: item_ids  int32  [B]
//  2: user_emb  f32    [U, 32]
//  3: item_emb  f32    [I, 32]
//  4: W_att     f32    [10, 32]
//  5: memory    f32    [10, 32]
// Output: f32 [B] = -sum((ue + rel - ie)^2)
//
// Each element is handled by a group of 8 lanes; lane `sub` owns dims
// [sub*4, sub*4+4) as one float4 per table. One warp processes 4 elements.
// 16384 elements * 8 lanes = 128K threads = 4096 warps (~28/SM resident).

#define M 10
#define THREADS_PER_BLOCK 128   // 4 warps -> 16 elements per block

__global__ __launch_bounds__(THREADS_PER_BLOCK)
void LRML_90804198572513_kernel(const int* __restrict__ user_ids,
                                const int* __restrict__ item_ids,
                                const float* __restrict__ user_emb,
                                const float* __restrict__ item_emb,
                                const float* __restrict__ W_att,
                                const float* __restrict__ memory,
                                float* __restrict__ out,
                                int B) {
    __shared__ float4 sW[M][8];   // W_att rows, 8 float4s each
    __shared__ float4 sM[M][8];   // memory rows

    for (int i = threadIdx.x; i < M * 8; i += THREADS_PER_BLOCK) {
        ((float4*)sW)[i] = ((const float4*)W_att)[i];
        ((float4*)sM)[i] = ((const float4*)memory)[i];
    }
    __syncthreads();

    const int lane = threadIdx.x & 31;
    const int warp = threadIdx.x >> 5;
    const int sub  = lane & 7;    // 4-dim slice owner (0..7)
    const int eg   = lane >> 3;   // element within warp (0..3)
    const int b = ((blockIdx.x * (THREADS_PER_BLOCK / 32) + warp) << 2) + eg;
    if (b >= B) return;

    const int uid = user_ids[b];
    const int iid = item_ids[b];

    // Coalesced gathers: lanes 0..7 of a group cover one full 128B row.
    const float4 u = ((const float4*)(user_emb + (size_t)uid * 32))[sub];
    const float4 iv = ((const float4*)(item_emb + (size_t)iid * 32))[sub];

    // Partial squared norms; all-reduce within the 8-lane group.
    float nu = u.x*u.x + u.y*u.y + u.z*u.z + u.w*u.w;
    float ni = iv.x*iv.x + iv.y*iv.y + iv.z*iv.z + iv.w*iv.w;
    #pragma unroll
    for (int o = 1; o <= 4; o <<= 1) {
        nu += __shfl_xor_sync(0xFFFFFFFFu, nu, o);
        ni += __shfl_xor_sync(0xFFFFFFFFu, ni, o);
    }

    // scale = 1 / max(||e||, 1) = min(rsqrt(n), 1)  (n=0 -> inf -> 1, fine)
    const float su = fminf(rsqrtf(nu), 1.0f);
    const float si = fminf(rsqrtf(ni), 1.0f);
    const float sj = su * si;

    // joint = (u*su) * (i*si) = (u*i) * (su*si) — no need to materialize ur/ir.
    float4 j;
    j.x = u.x*iv.x*sj; j.y = u.y*iv.y*sj; j.z = u.z*iv.z*sj; j.w = u.w*iv.w*sj;

    // scores[m] = <joint, W_att[m]>: per-lane 4-dim partial, 3 butterfly stages.
    float s[M];
    #pragma unroll
    for (int m = 0; m < M; m++) {
        const float4 w = sW[m][sub];
        s[m] = j.x*w.x + j.y*w.y + j.z*w.z + j.w*w.w;
    }
    #pragma unroll
    for (int o = 1; o <= 4; o <<= 1) {
        #pragma unroll
        for (int m = 0; m < M; m++)
            s[m] += __shfl_xor_sync(0xFFFFFFFFu, s[m], o);
    }

    // Softmax over M=10 (redundant per lane — cheap).
    float mx = s[0];
    #pragma unroll
    for (int m = 1; m < M; m++) mx = fmaxf(mx, s[m]);
    float sum = 0.0f;
    #pragma unroll
    for (int m = 0; m < M; m++) { s[m] = __expf(s[m] - mx); sum += s[m]; }
    const float inv = 1.0f / sum;

    // rel[d] = sum_m p[m] * memory[m][d] for this lane's 4 dims.
    float4 r = make_float4(0.f, 0.f, 0.f, 0.f);
    #pragma unroll
    for (int m = 0; m < M; m++) {
        const float p = s[m] * inv;
        const float4 mm = sM[m][sub];
        r.x = fmaf(p, mm.x, r.x); r.y = fmaf(p, mm.y, r.y);
        r.z = fmaf(p, mm.z, r.z); r.w = fmaf(p, mm.w, r.w);
    }

    // dist vec = su*u + rel - si*i ; accumulate squared, reduce over group.
    float dx, d = 0.0f;
    dx = fmaf(su, u.x, r.x) - si * iv.x; d = fmaf(dx, dx, d);
    dx = fmaf(su, u.y, r.y) - si * iv.y; d = fmaf(dx, dx, d);
    dx = fmaf(su, u.z, r.z) - si * iv.z; d = fmaf(dx, dx, d);
    dx = fmaf(su, u.w, r.w) - si * iv.w; d = fmaf(dx, dx, d);
    #pragma unroll
    for (int o = 1; o <= 4; o <<= 1)
        d += __shfl_xor_sync(0xFFFFFFFFu, d, o);

    if (sub == 0) out[b] = -d;
}

extern "C" void kernel_launch(void* const* d_in, const int* in_sizes, int n_in,
                              void* d_out, int out_size) {
    const int*   user_ids = (const int*)  d_in[0];
    const int*   item_ids = (const int*)  d_in[1];
    const float* user_emb = (const float*)d_in[2];
    const float* item_emb = (const float*)d_in[3];
    const float* W_att    = (const float*)d_in[4];
    const float* memory   = (const float*)d_in[5];
    float* out = (float*)d_out;

    const int B = in_sizes[0];
    const int elems_per_block = (THREADS_PER_BLOCK / 32) * 4;  // 16
    const int grid = (B + elems_per_block - 1) / elems_per_block;
    LRML_90804198572513_kernel<<<grid, THREADS_PER_BLOCK>>>(
        user_ids, item_ids, user_emb, item_emb, W_att, memory, out, B);
}